// round 5
// baseline (speedup 1.0000x reference)
#include <cuda_runtime.h>
#include <cuda_bf16.h>
#include <cstdint>

#define NB      32
#define NRINGS  10
#define NANG    36
#define NPTS    (NRINGS * NANG)       // 360
#define NTGT    16384
#define NGRP    ((NB * NTGT) / 32)    // 16384 groups of 32 targets
#define NBLK    444                   // 148 SMs x 3 resident blocks
#define NBIG    400                   // blocks with 37 groups (rest have 36)
#define TPB     (NRINGS * 32)         // 320: warp = ring
#define MAXT    (37 * 32)             // 1184

// Monotone-encoded running max of -d2 per (batch,point). Zero = -inf sentinel;
// last block resets after the reduce so graph replays see a clean state.
__device__ unsigned int g_keys[NB * NPTS];
__device__ unsigned int g_count;

__device__ __forceinline__ unsigned int enc_f32(float f) {
    unsigned int u = __float_as_uint(f);
    return ((int)u < 0) ? ~u : (u | 0x80000000u);
}
__device__ __forceinline__ float dec_f32(unsigned int k) {
    unsigned int u = ((int)k < 0) ? (k & 0x7FFFFFFFu) : ~k;
    return __uint_as_float(u);
}

// Paired angles (a, 36-a): shared-cos FFMA then +/-S*V. All constants FFMA imms.
#define PAIR2(IA, IB, CV, SV)                        \
    { float P = fmaf(CV, U, Acc);                    \
      m[IA] = fminf(m[IA], fmaf( SV, V, P));         \
      m[IB] = fminf(m[IB], fmaf(-SV, V, P)); }

// Pass A: global angles {0,18} + pairs 1..8  -> 18 local accumulators
__device__ __forceinline__ void evalA(float* m, float U, float V, float Acc) {
    m[0] = fminf(m[0], Acc + U);
    m[1] = fminf(m[1], Acc - U);
    PAIR2( 2,  3, 0.9848077530f, 0.1736481777f)
    PAIR2( 4,  5, 0.9396926208f, 0.3420201433f)
    PAIR2( 6,  7, 0.8660254038f, 0.5f)
    PAIR2( 8,  9, 0.7660444431f, 0.6427876097f)
    PAIR2(10, 11, 0.6427876097f, 0.7660444431f)
    PAIR2(12, 13, 0.5f,          0.8660254038f)
    PAIR2(14, 15, 0.3420201433f, 0.9396926208f)
    PAIR2(16, 17, 0.1736481777f, 0.9848077530f)
}
// Pass B: global angles {9,27} + pairs 10..17
__device__ __forceinline__ void evalB(float* m, float U, float V, float Acc) {
    m[0] = fminf(m[0], Acc + V);
    m[1] = fminf(m[1], Acc - V);
    PAIR2( 2,  3, -0.1736481777f, 0.9848077530f)
    PAIR2( 4,  5, -0.3420201433f, 0.9396926208f)
    PAIR2( 6,  7, -0.5f,          0.8660254038f)
    PAIR2( 8,  9, -0.6427876097f, 0.7660444431f)
    PAIR2(10, 11, -0.7660444431f, 0.6427876097f)
    PAIR2(12, 13, -0.8660254038f, 0.5f)
    PAIR2(14, 15, -0.9396926208f, 0.3420201433f)
    PAIR2(16, 17, -0.9848077530f, 0.1736481777f)
}

__device__ __constant__ int MAPA[18] = {0,18, 1,35, 2,34, 3,33, 4,32, 5,31, 6,30, 7,29, 8,28};
__device__ __constant__ int MAPB[18] = {9,27, 10,26, 11,25, 12,24, 13,23, 14,22, 15,21, 16,20, 17,19};

// One pass over the staged tile with 18 accumulators. NG/SPLIT compile-time.
template<int NG, bool SPLIT, int WHICH>
__device__ __forceinline__ void run_pass(
    const float4* __restrict__ sm, int lane, int bd,
    float r0, float Kr0, float r1, float Kr1, float py,
    unsigned int pbase0, unsigned int pbase1)
{
    const float INF = __int_as_float(0x7f800000);
    float m[18];
    #pragma unroll
    for (int a = 0; a < 18; a++) m[a] = INF;

    #pragma unroll 2
    for (int it = 0; it < NG; it++) {
        const int t = it * 32 + lane;
        float4 v = sm[t];
        float r  = r0, Kr = Kr0;
        if (SPLIT) {                       // batch uniform per iter (bd % 32 == 0)
            bool lo = (t < bd);
            r  = lo ? r0 : r1;
            Kr = lo ? Kr0 : Kr1;
        }
        float Acc = fmaf(py, v.y, v.w) + Kr;
        float U   = r * v.x;
        float V   = r * v.z;
        if (WHICH == 0) evalA(m, U, V, Acc);
        else            evalB(m, U, V, Acc);
    }

    // SPLIT blocks fold each half separately (masked re-run of the tail half).
    if (SPLIT) {
        // redo nothing: instead reduce per-lane minima that mixed batches is WRONG.
        // -> handled by caller splitting iterations; see run_block below.
    }
    #pragma unroll
    for (int a = 0; a < 18; a++) {
        float x = m[a];
        #pragma unroll
        for (int o = 16; o > 0; o >>= 1)
            x = fminf(x, __shfl_xor_sync(0xffffffffu, x, o));
        if (lane == a) {
            const int ga = (WHICH == 0) ? MAPA[a] : MAPB[a];
            atomicMax(&g_keys[pbase0 + ga], enc_f32(-x));
        }
    }
    (void)pbase1;
}

// SPLIT variant: two accumulator sets selected per iter would mix batches in the
// warp reduce, so run each batch's iter range with compile-time-striped loops.
template<int NG, int WHICH>
__device__ __forceinline__ void run_pass_split(
    const float4* __restrict__ sm, int lane, int bdIt,   // boundary in iters
    float r0, float Kr0, float r1, float Kr1, float py,
    unsigned int pbase0, unsigned int pbase1)
{
    const float INF = __int_as_float(0x7f800000);
    float m0[18], m1[18];
    #pragma unroll
    for (int a = 0; a < 18; a++) { m0[a] = INF; m1[a] = INF; }

    #pragma unroll 2
    for (int it = 0; it < NG; it++) {
        const int t = it * 32 + lane;
        float4 v = sm[t];
        bool lo = (it < bdIt);
        float r  = lo ? r0 : r1;
        float Kr = lo ? Kr0 : Kr1;
        float Acc = fmaf(py, v.y, v.w) + Kr;
        float U   = r * v.x;
        float V   = r * v.z;
        float* m = lo ? m0 : m1;
        if (WHICH == 0) evalA(m, U, V, Acc);
        else            evalB(m, U, V, Acc);
    }

    #pragma unroll
    for (int a = 0; a < 18; a++) {
        const int ga = (WHICH == 0) ? MAPA[a] : MAPB[a];
        float x = m0[a];
        #pragma unroll
        for (int o = 16; o > 0; o >>= 1)
            x = fminf(x, __shfl_xor_sync(0xffffffffu, x, o));
        if (lane == a) atomicMax(&g_keys[pbase0 + ga], enc_f32(-x));
        float y = m1[a];
        #pragma unroll
        for (int o = 16; o > 0; o >>= 1)
            y = fminf(y, __shfl_xor_sync(0xffffffffu, y, o));
        if (lane == a) atomicMax(&g_keys[pbase1 + ga], enc_f32(-y));
    }
}

template<int NG>
__device__ __forceinline__ void run_block(
    const float4* __restrict__ sm, const float* __restrict__ pred,
    int s0, int ring, int lane)
{
    const float py = 0.15f * (float)ring - 0.7f;
    const int   b0 = s0 >> 14;
    const int   n  = NG * 32;
    const int   bd = min(n, ((b0 + 1) << 14) - s0);   // multiple of 32

    const float r0  = pred[b0 * NRINGS + ring];
    const float Kr0 = fmaf(r0, r0, fmaf(py, py, 0.0016f));
    const unsigned int pb0 = (unsigned)(b0 * NPTS + ring * NANG);

    if (bd >= n) {
        run_pass<NG, false, 0>(sm, lane, 0, r0, Kr0, 0.f, 0.f, py, pb0, 0u);
        run_pass<NG, false, 1>(sm, lane, 0, r0, Kr0, 0.f, 0.f, py, pb0, 0u);
    } else {
        const float r1  = pred[(b0 + 1) * NRINGS + ring];
        const float Kr1 = fmaf(r1, r1, fmaf(py, py, 0.0016f));
        const unsigned int pb1 = pb0 + NPTS;
        const int bdIt = bd >> 5;
        run_pass_split<NG, 0>(sm, lane, bdIt, r0, Kr0, r1, Kr1, py, pb0, pb1);
        run_pass_split<NG, 1>(sm, lane, bdIt, r0, Kr0, r1, Kr1, py, pb0, pb1);
    }
}

__global__ void __launch_bounds__(TPB)
chamfer_fused_kernel(const float* __restrict__ pred,
                     const float* __restrict__ target,
                     float* __restrict__ out)
{
    __shared__ float4 sm[MAXT];
    __shared__ float  wsum[NRINGS];
    __shared__ unsigned int is_last;

    const int bid = blockIdx.x;
    const int tid = threadIdx.x;

    const bool big = (bid < NBIG);
    const int  g0  = big ? bid * 37 : NBIG * 37 + (bid - NBIG) * 36;
    const int  ng  = big ? 37 : 36;
    const int  s0  = g0 * 32;
    const int  n   = ng * 32;

    // Stage + preprocess: (2tx-0.08, -2ty, -2tz, t2-0.08tx)
    const float* tg = target + (size_t)s0 * 3;
    for (int i = tid; i < n; i += TPB) {
        float tx = tg[i * 3 + 0];
        float ty = tg[i * 3 + 1];
        float tz = tg[i * 3 + 2];
        float t2 = tx * tx + ty * ty + tz * tz;
        sm[i] = make_float4(2.0f * tx - 0.08f, -2.0f * ty, -2.0f * tz,
                            fmaf(-0.08f, tx, t2));
    }
    __syncthreads();

    const int ring = tid >> 5;
    const int lane = tid & 31;

    if (big) run_block<37>(sm, pred, s0, ring, lane);
    else     run_block<36>(sm, pred, s0, ring, lane);

    // ---- last-block finalize ----
    __threadfence();
    if (tid == 0)
        is_last = (atomicAdd(&g_count, 1u) == (unsigned)(NBLK - 1));
    __syncthreads();
    if (!is_last) return;
    __threadfence();

    uint4* keys4 = (uint4*)g_keys;
    const int n4 = (NB * NPTS) / 4;
    float s = 0.0f;
    for (int i = tid; i < n4; i += TPB) {
        uint4 k = keys4[i];
        s += fmaxf(-dec_f32(k.x), 0.0f);
        s += fmaxf(-dec_f32(k.y), 0.0f);
        s += fmaxf(-dec_f32(k.z), 0.0f);
        s += fmaxf(-dec_f32(k.w), 0.0f);
    }
    #pragma unroll
    for (int o = 16; o > 0; o >>= 1) s += __shfl_down_sync(0xffffffffu, s, o);
    if (lane == 0) wsum[ring] = s;
    __syncthreads();
    if (tid == 0) {
        float tot = 0.0f;
        #pragma unroll
        for (int w = 0; w < NRINGS; w++) tot += wsum[w];
        out[0] = tot / (float)(NB * NPTS);
    }
    __syncthreads();

    const uint4 z4 = make_uint4(0u, 0u, 0u, 0u);
    for (int i = tid; i < n4; i += TPB) keys4[i] = z4;
    if (tid == 0) g_count = 0u;
}

extern "C" void kernel_launch(void* const* d_in, const int* in_sizes, int n_in,
                              void* d_out, int out_size) {
    const float* pred   = (const float*)d_in[0];   // (32, 10)
    const float* target = (const float*)d_in[1];   // (32, 16384, 3)
    float* out = (float*)d_out;

    chamfer_fused_kernel<<<NBLK, TPB>>>(pred, target, out);
}

// round 6
// speedup vs baseline: 1.4992x; 1.4992x over previous
#include <cuda_runtime.h>
#include <cuda_bf16.h>
#include <cstdint>

#define NB      32
#define NRINGS  10
#define NANG    36
#define NPTS    (NRINGS * NANG)     // 360
#define NTGT    16384
#define NCHUNK  16
#define TC      (NTGT / NCHUNK)     // 1024 targets per chunk (compile-time)
#define TPB     (NRINGS * 32)       // 320 threads: warp = ring
#define NBLK    (NCHUNK * NB)       // 512 blocks

// Monotone-encoded running max of -d2 per (batch,point). Zero = -inf sentinel;
// the last block resets everything after the reduce so graph replays are clean.
__device__ unsigned int g_keys[NB * NPTS];
__device__ unsigned int g_count;

__device__ __forceinline__ unsigned int enc_f32(float f) {
    unsigned int u = __float_as_uint(f);
    return ((int)u < 0) ? ~u : (u | 0x80000000u);
}
__device__ __forceinline__ float dec_f32(unsigned int k) {
    unsigned int u = ((int)k < 0) ? (k & 0x7FFFFFFFu) : ~k;
    return __uint_as_float(u);
}

// Paired angles (a, 36-a): shared-cos FFMA, then +/-S*V. Constants = FFMA imms.
#define PAIR2(IA, IB, CV, SV)                        \
    { float P = fmaf(CV, U, Acc);                    \
      m[IA] = fminf(m[IA], fmaf( SV, V, P));         \
      m[IB] = fminf(m[IB], fmaf(-SV, V, P)); }

// Pass A covers global angles {0,18, 1,35, 2,34, 3,33, 4,32, 5,31, 6,30, 7,29, 8,28}
__device__ __forceinline__ void evalA(float m[18], float U, float V, float Acc) {
    m[0] = fminf(m[0], Acc + U);
    m[1] = fminf(m[1], Acc - U);
    PAIR2( 2,  3, 0.9848077530f, 0.1736481777f)
    PAIR2( 4,  5, 0.9396926208f, 0.3420201433f)
    PAIR2( 6,  7, 0.8660254038f, 0.5f)
    PAIR2( 8,  9, 0.7660444431f, 0.6427876097f)
    PAIR2(10, 11, 0.6427876097f, 0.7660444431f)
    PAIR2(12, 13, 0.5f,          0.8660254038f)
    PAIR2(14, 15, 0.3420201433f, 0.9396926208f)
    PAIR2(16, 17, 0.1736481777f, 0.9848077530f)
}
// Pass B covers global angles {9,27, 10,26, 11,25, 12,24, 13,23, 14,22, 15,21, 16,20, 17,19}
__device__ __forceinline__ void evalB(float m[18], float U, float V, float Acc) {
    m[0] = fminf(m[0], Acc + V);
    m[1] = fminf(m[1], Acc - V);
    PAIR2( 2,  3, -0.1736481777f, 0.9848077530f)
    PAIR2( 4,  5, -0.3420201433f, 0.9396926208f)
    PAIR2( 6,  7, -0.5f,          0.8660254038f)
    PAIR2( 8,  9, -0.6427876097f, 0.7660444431f)
    PAIR2(10, 11, -0.7660444431f, 0.6427876097f)
    PAIR2(12, 13, -0.8660254038f, 0.5f)
    PAIR2(14, 15, -0.9396926208f, 0.3420201433f)
    PAIR2(16, 17, -0.9848077530f, 0.1736481777f)
}

__device__ __constant__ unsigned char MAPA[18] =
    {0,18, 1,35, 2,34, 3,33, 4,32, 5,31, 6,30, 7,29, 8,28};
__device__ __constant__ unsigned char MAPB[18] =
    {9,27, 10,26, 11,25, 12,24, 13,23, 14,22, 15,21, 16,20, 17,19};

// Warp-reduce 18 minima and fold into g_keys via REDG.MAX (deterministic).
__device__ __forceinline__ void fold18(const float m[18], int lane,
                                       unsigned int pbase,
                                       const unsigned char* map) {
    #pragma unroll
    for (int a = 0; a < 18; a++) {
        float x = m[a];
        #pragma unroll
        for (int o = 16; o > 0; o >>= 1)
            x = fminf(x, __shfl_xor_sync(0xffffffffu, x, o));
        if (lane == a)
            atomicMax(&g_keys[pbase + map[a]], enc_f32(-x));
    }
}

__global__ void __launch_bounds__(TPB, 4)
chamfer_fused_kernel(const float* __restrict__ pred,
                     const float* __restrict__ target,
                     float* __restrict__ out)
{
    __shared__ float4 sm[TC];
    __shared__ float  wsum[NRINGS];
    __shared__ unsigned int is_last;

    const int chunk = blockIdx.x;
    const int b     = blockIdx.y;
    const int tid   = threadIdx.x;

    // Stage + preprocess: (2tx-0.08, -2ty, -2tz, t2-0.08tx)
    const float* tg = target + ((size_t)b * NTGT + (size_t)chunk * TC) * 3;
    for (int i = tid; i < TC; i += TPB) {
        float tx = tg[i * 3 + 0];
        float ty = tg[i * 3 + 1];
        float tz = tg[i * 3 + 2];
        float t2 = tx * tx + ty * ty + tz * tz;
        sm[i] = make_float4(2.0f * tx - 0.08f, -2.0f * ty, -2.0f * tz,
                            fmaf(-0.08f, tx, t2));
    }
    __syncthreads();

    const int ring = tid >> 5;
    const int lane = tid & 31;

    const float r  = pred[b * NRINGS + ring];
    const float py = 0.15f * (float)ring - 0.7f;
    const float Kr = fmaf(r, r, fmaf(py, py, 0.0016f));
    const unsigned int pbase = (unsigned)(b * NPTS + ring * NANG);
    const float INF = __int_as_float(0x7f800000);

    // ---- Pass A: 18 accumulators (register-light; compile-time bounds) ----
    {
        float m[18];
        #pragma unroll
        for (int a = 0; a < 18; a++) m[a] = INF;
        #pragma unroll 2
        for (int t = lane; t < TC; t += 32) {
            float4 v  = sm[t];
            float Acc = fmaf(py, v.y, v.w) + Kr;
            float U   = r * v.x;
            float V   = r * v.z;
            evalA(m, U, V, Acc);
        }
        fold18(m, lane, pbase, MAPA);
    }
    // ---- Pass B ----
    {
        float m[18];
        #pragma unroll
        for (int a = 0; a < 18; a++) m[a] = INF;
        #pragma unroll 2
        for (int t = lane; t < TC; t += 32) {
            float4 v  = sm[t];
            float Acc = fmaf(py, v.y, v.w) + Kr;
            float U   = r * v.x;
            float V   = r * v.z;
            evalB(m, U, V, Acc);
        }
        fold18(m, lane, pbase, MAPB);
    }

    // ---- last-block finalize (fused; no second kernel) ----
    __threadfence();
    if (tid == 0)
        is_last = (atomicAdd(&g_count, 1u) == (unsigned)(NBLK - 1));
    __syncthreads();
    if (!is_last) return;
    __threadfence();

    uint4* keys4 = (uint4*)g_keys;
    const int n4 = (NB * NPTS) / 4;     // 2880
    float s = 0.0f;
    for (int i = tid; i < n4; i += TPB) {
        uint4 k = keys4[i];
        s += fmaxf(-dec_f32(k.x), 0.0f);
        s += fmaxf(-dec_f32(k.y), 0.0f);
        s += fmaxf(-dec_f32(k.z), 0.0f);
        s += fmaxf(-dec_f32(k.w), 0.0f);
    }
    #pragma unroll
    for (int o = 16; o > 0; o >>= 1) s += __shfl_down_sync(0xffffffffu, s, o);
    if (lane == 0) wsum[ring] = s;
    __syncthreads();
    if (tid == 0) {
        float tot = 0.0f;
        #pragma unroll
        for (int w = 0; w < NRINGS; w++) tot += wsum[w];
        out[0] = tot / (float)(NB * NPTS);
    }
    __syncthreads();   // all g_keys reads complete before reset

    const uint4 z4 = make_uint4(0u, 0u, 0u, 0u);
    for (int i = tid; i < n4; i += TPB) keys4[i] = z4;
    if (tid == 0) g_count = 0u;
}

extern "C" void kernel_launch(void* const* d_in, const int* in_sizes, int n_in,
                              void* d_out, int out_size) {
    const float* pred   = (const float*)d_in[0];   // (32, 10)
    const float* target = (const float*)d_in[1];   // (32, 16384, 3)
    float* out = (float*)d_out;

    dim3 grid(NCHUNK, NB);
    chamfer_fused_kernel<<<grid, TPB>>>(pred, target, out);
}

// round 7
// speedup vs baseline: 1.6854x; 1.1242x over previous
#include <cuda_runtime.h>
#include <cuda_bf16.h>
#include <cstdint>

#define NB      32
#define NRINGS  10
#define NANG    36
#define NPTS    (NRINGS * NANG)     // 360
#define NTGT    16384
#define NCHUNK  16
#define TC      (NTGT / NCHUNK)     // 1024 targets per chunk
#define NPAIR   (TC / 2)            // 512 packed target pairs
#define TPB     (NRINGS * 32)       // 320 threads: warp = ring
#define NBLK    (NCHUNK * NB)       // 512 blocks

// Monotone-encoded running max of -d2 per (batch,point). Zero = -inf sentinel;
// last block resets after the reduce so graph replays see a clean state.
__device__ unsigned int g_keys[NB * NPTS];
__device__ unsigned int g_count;

__device__ __forceinline__ unsigned int enc_f32(float f) {
    unsigned int u = __float_as_uint(f);
    return ((int)u < 0) ? ~u : (u | 0x80000000u);
}
__device__ __forceinline__ float dec_f32(unsigned int k) {
    unsigned int u = ((int)k < 0) ? (k & 0x7FFFFFFFu) : ~k;
    return __uint_as_float(u);
}

// ---- packed f32x2 primitives (Blackwell FFMA2/FMUL2/FADD2 path) ----
typedef unsigned long long ull;
__device__ __forceinline__ ull pack2(float lo, float hi) {
    ull r; asm("mov.b64 %0, {%1,%2};" : "=l"(r) : "f"(lo), "f"(hi)); return r;
}
__device__ __forceinline__ ull mul2(ull a, ull b) {
    ull d; asm("mul.rn.f32x2 %0, %1, %2;" : "=l"(d) : "l"(a), "l"(b)); return d;
}
__device__ __forceinline__ ull add2(ull a, ull b) {
    ull d; asm("add.rn.f32x2 %0, %1, %2;" : "=l"(d) : "l"(a), "l"(b)); return d;
}
__device__ __forceinline__ ull fma2(ull a, ull b, ull c) {
    ull d; asm("fma.rn.f32x2 %0, %1, %2, %3;" : "=l"(d) : "l"(a), "l"(b), "l"(c)); return d;
}
__device__ __forceinline__ float hmin2(ull a) {    // min of the two packed halves
    float lo, hi; asm("mov.b64 {%0,%1}, %2;" : "=f"(lo), "=f"(hi) : "l"(a));
    return fminf(lo, hi);
}

// d2 for a mirror pair: P = fma2(Cm, Uop, A2); then +/-S*V via V2/nV2.
#define PPAIR(IA, IB, Cm, Uop, Sm)                                   \
    { ull P = fma2(Cm, Uop, A2);                                     \
      m[IA] = fminf(m[IA], hmin2(fma2(Sm, V2,  P)));                 \
      m[IB] = fminf(m[IB], hmin2(fma2(Sm, nV2, P))); }

// local accumulator index -> global angle id
__device__ __constant__ unsigned char MAPA[18] =
    {0,18, 1,35, 8,28, 2,34, 7,29, 3,33, 6,30, 4,32, 5,31};
__device__ __constant__ unsigned char MAPB[18] =
    {9,27, 10,26, 17,19, 11,25, 16,20, 12,24, 15,21, 13,23, 14,22};

__device__ __forceinline__ void fold18(const float m[18], int lane,
                                       unsigned int pbase,
                                       const unsigned char* map) {
    #pragma unroll
    for (int a = 0; a < 18; a++) {
        float x = m[a];
        #pragma unroll
        for (int o = 16; o > 0; o >>= 1)
            x = fminf(x, __shfl_xor_sync(0xffffffffu, x, o));
        if (lane == a)
            atomicMax(&g_keys[pbase + map[a]], enc_f32(-x));
    }
}

__global__ void __launch_bounds__(TPB)
chamfer_fused_kernel(const float* __restrict__ pred,
                     const float* __restrict__ target,
                     float* __restrict__ out)
{
    // pair-interleaved SoA: s_ey[p] = (e0,e1,y0,y1), s_zw[p] = (z0,z1,w0,w1)
    __shared__ float4 s_ey[NPAIR];
    __shared__ float4 s_zw[NPAIR];
    __shared__ float  wsum[NRINGS];
    __shared__ unsigned int is_last;

    const int chunk = blockIdx.x;
    const int b     = blockIdx.y;
    const int tid   = threadIdx.x;

    // Stage + preprocess: e=2tx-0.08, y=-2ty, z=-2tz, w=t2-0.08tx
    const float* tg = target + ((size_t)b * NTGT + (size_t)chunk * TC) * 3;
    float* fey = (float*)s_ey;
    float* fzw = (float*)s_zw;
    for (int i = tid; i < TC; i += TPB) {
        float tx = tg[i * 3 + 0];
        float ty = tg[i * 3 + 1];
        float tz = tg[i * 3 + 2];
        float t2 = tx * tx + ty * ty + tz * tz;
        int p = i >> 1, h = i & 1;
        fey[4 * p + h]     = 2.0f * tx - 0.08f;
        fey[4 * p + 2 + h] = -2.0f * ty;
        fzw[4 * p + h]     = -2.0f * tz;
        fzw[4 * p + 2 + h] = fmaf(-0.08f, tx, t2);
    }
    __syncthreads();

    const int ring = tid >> 5;
    const int lane = tid & 31;

    const float r  = pred[b * NRINGS + ring];
    const float py = 0.15f * (float)ring - 0.7f;
    const float Kr = fmaf(r, r, fmaf(py, py, 0.0016f));
    const unsigned int pbase = (unsigned)(b * NPTS + ring * NANG);
    const float INF = __int_as_float(0x7f800000);

    const ull r2  = pack2(r, r);
    const ull nr2 = pack2(-r, -r);
    const ull py2 = pack2(py, py);
    const ull Kr2 = pack2(Kr, Kr);

    // 4 magnitude pairs cover all 36 angles (cos80=sin10 etc.)
    const ull C10 = pack2(0.9848077530122080f, 0.9848077530122080f);
    const ull S10 = pack2(0.1736481776669303f, 0.1736481776669303f);
    const ull C20 = pack2(0.9396926207859084f, 0.9396926207859084f);
    const ull S20 = pack2(0.3420201433256687f, 0.3420201433256687f);
    const ull C30 = pack2(0.8660254037844387f, 0.8660254037844387f);
    const ull S30 = pack2(0.5f, 0.5f);
    const ull C40 = pack2(0.7660444431189780f, 0.7660444431189780f);
    const ull S40 = pack2(0.6427876096865393f, 0.6427876096865393f);

    // ---- Pass A: angles {0,18} + mirror pairs using +cos on U ----
    {
        float m[18];
        #pragma unroll
        for (int a = 0; a < 18; a++) m[a] = INF;

        #pragma unroll 2
        for (int it = 0; it < NPAIR / 32; it++) {
            const int p = it * 32 + lane;
            float4 vey = s_ey[p];
            float4 vzw = s_zw[p];
            ull e2 = pack2(vey.x, vey.y);
            ull y2 = pack2(vey.z, vey.w);
            ull z2 = pack2(vzw.x, vzw.y);
            ull w2 = pack2(vzw.z, vzw.w);
            ull U2  = mul2(r2,  e2);
            ull nU2 = mul2(nr2, e2);
            ull V2  = mul2(r2,  z2);
            ull nV2 = mul2(nr2, z2);
            ull A2  = add2(fma2(py2, y2, w2), Kr2);

            m[0] = fminf(m[0], hmin2(add2(A2, U2)));    // angle 0
            m[1] = fminf(m[1], hmin2(add2(A2, nU2)));   // angle 18 (180 deg)
            PPAIR( 2,  3, C10, U2, S10)   // (1, 35)
            PPAIR( 4,  5, S10, U2, C10)   // (8, 28): cos80=sin10
            PPAIR( 6,  7, C20, U2, S20)   // (2, 34)
            PPAIR( 8,  9, S20, U2, C20)   // (7, 29)
            PPAIR(10, 11, C30, U2, S30)   // (3, 33)
            PPAIR(12, 13, S30, U2, C30)   // (6, 30)
            PPAIR(14, 15, C40, U2, S40)   // (4, 32)
            PPAIR(16, 17, S40, U2, C40)   // (5, 31)
        }
        fold18(m, lane, pbase, MAPA);
    }

    // ---- Pass B: angles {9,27} + mirror pairs using -cos on U (via nU2) ----
    {
        float m[18];
        #pragma unroll
        for (int a = 0; a < 18; a++) m[a] = INF;

        #pragma unroll 2
        for (int it = 0; it < NPAIR / 32; it++) {
            const int p = it * 32 + lane;
            float4 vey = s_ey[p];
            float4 vzw = s_zw[p];
            ull e2 = pack2(vey.x, vey.y);
            ull y2 = pack2(vey.z, vey.w);
            ull z2 = pack2(vzw.x, vzw.y);
            ull w2 = pack2(vzw.z, vzw.w);
            ull U2  = mul2(r2,  e2);   (void)U2;
            ull nU2 = mul2(nr2, e2);
            ull V2  = mul2(r2,  z2);
            ull nV2 = mul2(nr2, z2);
            ull A2  = add2(fma2(py2, y2, w2), Kr2);

            m[0] = fminf(m[0], hmin2(add2(A2, V2)));    // angle 9  (90 deg)
            m[1] = fminf(m[1], hmin2(add2(A2, nV2)));   // angle 27 (270 deg)
            PPAIR( 2,  3, S10, nU2, C10)  // (10, 26): cos100=-sin10, sin100=cos10
            PPAIR( 4,  5, C10, nU2, S10)  // (17, 19): cos170=-cos10
            PPAIR( 6,  7, S20, nU2, C20)  // (11, 25)
            PPAIR( 8,  9, C20, nU2, S20)  // (16, 20)
            PPAIR(10, 11, S30, nU2, C30)  // (12, 24)
            PPAIR(12, 13, C30, nU2, S30)  // (15, 21)
            PPAIR(14, 15, S40, nU2, C40)  // (13, 23)
            PPAIR(16, 17, C40, nU2, S40)  // (14, 22)
        }
        fold18(m, lane, pbase, MAPB);
    }

    // ---- last-block finalize (fused) ----
    __threadfence();
    if (tid == 0)
        is_last = (atomicAdd(&g_count, 1u) == (unsigned)(NBLK - 1));
    __syncthreads();
    if (!is_last) return;
    __threadfence();

    uint4* keys4 = (uint4*)g_keys;
    const int n4 = (NB * NPTS) / 4;     // 2880
    float s = 0.0f;
    for (int i = tid; i < n4; i += TPB) {
        uint4 k = keys4[i];
        s += fmaxf(-dec_f32(k.x), 0.0f);
        s += fmaxf(-dec_f32(k.y), 0.0f);
        s += fmaxf(-dec_f32(k.z), 0.0f);
        s += fmaxf(-dec_f32(k.w), 0.0f);
    }
    #pragma unroll
    for (int o = 16; o > 0; o >>= 1) s += __shfl_down_sync(0xffffffffu, s, o);
    if (lane == 0) wsum[ring] = s;
    __syncthreads();
    if (tid == 0) {
        float tot = 0.0f;
        #pragma unroll
        for (int w = 0; w < NRINGS; w++) tot += wsum[w];
        out[0] = tot / (float)(NB * NPTS);
    }
    __syncthreads();   // all g_keys reads complete before reset

    const uint4 z4 = make_uint4(0u, 0u, 0u, 0u);
    for (int i = tid; i < n4; i += TPB) keys4[i] = z4;
    if (tid == 0) g_count = 0u;
}

extern "C" void kernel_launch(void* const* d_in, const int* in_sizes, int n_in,
                              void* d_out, int out_size) {
    const float* pred   = (const float*)d_in[0];   // (32, 10)
    const float* target = (const float*)d_in[1];   // (32, 16384, 3)
    float* out = (float*)d_out;

    dim3 grid(NCHUNK, NB);
    chamfer_fused_kernel<<<grid, TPB>>>(pred, target, out);
}